// round 1
// baseline (speedup 1.0000x reference)
#include <cuda_runtime.h>

#define B_ 256
#define I_ 512
#define R_ 512
#define A_ 196
#define V_ 10000

// ---------------- scratch (no allocation allowed) ----------------
__device__ float g_ah[B_ * A_];       // [B, A]  h-projection (per-row additive term)
__device__ float g_scores[B_ * A_];   // [B, A]
__device__ float g_attres[B_ * R_];   // [B, R]
__device__ float g_sums[B_ * 4 * R_]; // [B, 4R]
__device__ float g_nexth[B_ * R_];    // [B, R]

// ---------------- generic tiled SGEMM: C[m,n] = sum_k A[m,k]*B[n,k] + b1[n] (+b2[n]) ----------------
__device__ __forceinline__ void sgemm_body(
    const float* __restrict__ Am, const float* __restrict__ Bm,
    const float* __restrict__ b1, const float* __restrict__ b2,
    float* __restrict__ C, int M, int N, int K)
{
    __shared__ __align__(16) float As[16][68];
    __shared__ __align__(16) float Bs[16][68];
    const int m0 = blockIdx.y * 64, n0 = blockIdx.x * 64;
    const int tid = threadIdx.x;
    const int tn = tid & 15, tm = tid >> 4;
    const int lrow = tid >> 2, lc = (tid & 3) << 2;

    float acc[4][4] = {};
    for (int k0 = 0; k0 < K; k0 += 16) {
        float4 av = make_float4(0.f, 0.f, 0.f, 0.f);
        float4 bv = make_float4(0.f, 0.f, 0.f, 0.f);
        if (m0 + lrow < M) av = *(const float4*)(Am + (size_t)(m0 + lrow) * K + k0 + lc);
        if (n0 + lrow < N) bv = *(const float4*)(Bm + (size_t)(n0 + lrow) * K + k0 + lc);
        __syncthreads();
        As[lc + 0][lrow] = av.x; As[lc + 1][lrow] = av.y; As[lc + 2][lrow] = av.z; As[lc + 3][lrow] = av.w;
        Bs[lc + 0][lrow] = bv.x; Bs[lc + 1][lrow] = bv.y; Bs[lc + 2][lrow] = bv.z; Bs[lc + 3][lrow] = bv.w;
        __syncthreads();
#pragma unroll
        for (int kk = 0; kk < 16; kk++) {
            float a[4], b[4];
            *(float4*)a = *(const float4*)&As[kk][tm << 2];
            *(float4*)b = *(const float4*)&Bs[kk][tn << 2];
#pragma unroll
            for (int i = 0; i < 4; i++)
#pragma unroll
                for (int j = 0; j < 4; j++)
                    acc[i][j] += a[i] * b[j];
        }
    }
#pragma unroll
    for (int j = 0; j < 4; j++) {
        int n = n0 + (tn << 2) + j;
        if (n >= N) continue;
        float bias = (b1 ? b1[n] : 0.f) + (b2 ? b2[n] : 0.f);
#pragma unroll
        for (int i = 0; i < 4; i++) {
            int m = m0 + (tm << 2) + i;
            if (m < M) C[(size_t)m * N + n] = acc[i][j] + bias;
        }
    }
}

__global__ void __launch_bounds__(256, 2) sgemm_bias(
    const float* __restrict__ Am, const float* __restrict__ Bm,
    const float* __restrict__ b1, const float* __restrict__ b2,
    float* __restrict__ C, int M, int N, int K)
{
    sgemm_body(Am, Bm, b1, b2, C, M, N, K);
}

// ---------------- gates: sums = x@Wi^T + h@Wh^T + ar@Wa^T + (bi+bh+ba) ----------------
__global__ void __launch_bounds__(256, 2) gates_gemm(
    const float* __restrict__ x,  const float* __restrict__ Wi,
    const float* __restrict__ h,  const float* __restrict__ Wh,
    const float* __restrict__ ar, const float* __restrict__ Wa,
    const float* __restrict__ b1, const float* __restrict__ b2, const float* __restrict__ b3)
{
    __shared__ __align__(16) float As[16][68];
    __shared__ __align__(16) float Bs[16][68];
    const int m0 = blockIdx.y * 64, n0 = blockIdx.x * 64;  // M=256, N=2048, no tails
    const int tid = threadIdx.x;
    const int tn = tid & 15, tm = tid >> 4;
    const int lrow = tid >> 2, lc = (tid & 3) << 2;

    float acc[4][4] = {};
#pragma unroll 1
    for (int p = 0; p < 3; p++) {
        const float* Am = (p == 0) ? x : (p == 1) ? h : ar;
        const float* Bm = (p == 0) ? Wi : (p == 1) ? Wh : Wa;
        for (int k0 = 0; k0 < R_; k0 += 16) {
            float4 av = *(const float4*)(Am + (size_t)(m0 + lrow) * R_ + k0 + lc);
            float4 bv = *(const float4*)(Bm + (size_t)(n0 + lrow) * R_ + k0 + lc);
            __syncthreads();
            As[lc + 0][lrow] = av.x; As[lc + 1][lrow] = av.y; As[lc + 2][lrow] = av.z; As[lc + 3][lrow] = av.w;
            Bs[lc + 0][lrow] = bv.x; Bs[lc + 1][lrow] = bv.y; Bs[lc + 2][lrow] = bv.z; Bs[lc + 3][lrow] = bv.w;
            __syncthreads();
#pragma unroll
            for (int kk = 0; kk < 16; kk++) {
                float a[4], b[4];
                *(float4*)a = *(const float4*)&As[kk][tm << 2];
                *(float4*)b = *(const float4*)&Bs[kk][tn << 2];
#pragma unroll
                for (int i = 0; i < 4; i++)
#pragma unroll
                    for (int j = 0; j < 4; j++)
                        acc[i][j] += a[i] * b[j];
            }
        }
    }
#pragma unroll
    for (int j = 0; j < 4; j++) {
        int n = n0 + (tn << 2) + j;
        float bias = b1[n] + b2[n] + b3[n];
#pragma unroll
        for (int i = 0; i < 4; i++) {
            int m = m0 + (tm << 2) + i;
            g_sums[(size_t)m * (4 * R_) + n] = acc[i][j] + bias;
        }
    }
}

// ---------------- fused attend scores ----------------
// One dense GEMM over M = B*A = 50176 rows (att is contiguous [B*A, R]).
// scores[m] = bd + sum_o tanh( att_row[m]·Wa[o] + ba[o] + ah[m] ) * Wd[o]
__global__ void __launch_bounds__(256, 2) attend_scores(
    const float* __restrict__ att, const float* __restrict__ Wa,
    const float* __restrict__ ba,  const float* __restrict__ Wd,
    const float* __restrict__ bd)
{
    __shared__ __align__(16) float As[16][68];
    __shared__ __align__(16) float Bs[16][260];
    __shared__ float preds[64][17];
    const int m0 = blockIdx.x * 64;          // 50176 / 64 = 784 exact, no M tail
    const int tid = threadIdx.x;
    const int tn = tid & 15, tm = tid >> 4;
    const int lrow = tid >> 2, lc = (tid & 3) << 2;

    float acc[4][16] = {};
    for (int k0 = 0; k0 < R_; k0 += 16) {
        float4 av = *(const float4*)(att + (size_t)(m0 + lrow) * R_ + k0 + lc);
        float4 bv[4];
#pragma unroll
        for (int u = 0; u < 4; u++) {
            int br = lrow + (u << 6);
            bv[u] = (br < A_) ? *(const float4*)(Wa + (size_t)br * R_ + k0 + lc)
                              : make_float4(0.f, 0.f, 0.f, 0.f);
        }
        __syncthreads();
        As[lc + 0][lrow] = av.x; As[lc + 1][lrow] = av.y; As[lc + 2][lrow] = av.z; As[lc + 3][lrow] = av.w;
#pragma unroll
        for (int u = 0; u < 4; u++) {
            int br = lrow + (u << 6);
            Bs[lc + 0][br] = bv[u].x; Bs[lc + 1][br] = bv[u].y; Bs[lc + 2][br] = bv[u].z; Bs[lc + 3][br] = bv[u].w;
        }
        __syncthreads();
#pragma unroll
        for (int kk = 0; kk < 16; kk++) {
            float a[4];
            *(float4*)a = *(const float4*)&As[kk][tm << 2];
#pragma unroll
            for (int ot = 0; ot < 4; ot++) {
                float b[4];
                *(float4*)b = *(const float4*)&Bs[kk][(ot << 6) + (tn << 2)];
#pragma unroll
                for (int i = 0; i < 4; i++)
#pragma unroll
                    for (int j = 0; j < 4; j++)
                        acc[i][(ot << 2) + j] += a[i] * b[j];
            }
        }
    }

    // epilogue: tanh + weighted reduction over o (N dim)
    float ahv[4];
#pragma unroll
    for (int i = 0; i < 4; i++) ahv[i] = g_ah[m0 + (tm << 2) + i];

    float part[4] = {0.f, 0.f, 0.f, 0.f};
#pragma unroll
    for (int ot = 0; ot < 4; ot++)
#pragma unroll
        for (int j = 0; j < 4; j++) {
            int o = (ot << 6) + (tn << 2) + j;
            if (o < A_) {
                float wdo = Wd[o];
                float bao = ba[o];
#pragma unroll
                for (int i = 0; i < 4; i++)
                    part[i] += tanhf(acc[i][(ot << 2) + j] + bao + ahv[i]) * wdo;
            }
        }
    // deterministic tree reduction across the 16 tn-lanes
#pragma unroll
    for (int i = 0; i < 4; i++) preds[(tm << 2) + i][tn] = part[i];
    __syncthreads();
    if (tid < 64) {
        float s = bd[0];
#pragma unroll
        for (int t = 0; t < 16; t++) s += preds[tid][t];
        g_scores[m0 + tid] = s;
    }
}

// ---------------- softmax over a + weighted sum of att rows ----------------
__global__ void attend_apply(const float* __restrict__ att, float* __restrict__ outres)
{
    const int b = blockIdx.x, tid = threadIdx.x;  // 256 threads
    __shared__ float w[A_];
    __shared__ float rbuf[256];

    float s = (tid < A_) ? g_scores[b * A_ + tid] : -1e30f;
    rbuf[tid] = s;
    __syncthreads();
    for (int off = 128; off > 0; off >>= 1) {
        if (tid < off) rbuf[tid] = fmaxf(rbuf[tid], rbuf[tid + off]);
        __syncthreads();
    }
    float mx = rbuf[0];
    __syncthreads();
    float e = (tid < A_) ? __expf(s - mx) : 0.f;
    rbuf[tid] = e;
    __syncthreads();
    for (int off = 128; off > 0; off >>= 1) {
        if (tid < off) rbuf[tid] += rbuf[tid + off];
        __syncthreads();
    }
    float inv = 1.f / rbuf[0];
    if (tid < A_) w[tid] = e * inv;
    __syncthreads();

    const float* ab = att + (size_t)b * A_ * R_;
    for (int r = tid; r < R_; r += 256) {
        float acc = 0.f;
#pragma unroll 4
        for (int a = 0; a < A_; a++) acc += ab[a * R_ + r] * w[a];
        outres[b * R_ + r] = acc;
    }
}

// ---------------- LSTM cell ----------------
__global__ void lstm_cell(const float* __restrict__ prev_c, float* __restrict__ out_c)
{
    int idx = blockIdx.x * 256 + threadIdx.x;
    if (idx >= B_ * R_) return;
    int b = idx >> 9, j = idx & (R_ - 1);
    const float* s = g_sums + (size_t)b * 4 * R_;
    float ig = 1.f / (1.f + __expf(-s[j]));
    float fg = 1.f / (1.f + __expf(-s[R_ + j]));
    float og = 1.f / (1.f + __expf(-s[2 * R_ + j]));
    float gt = tanhf(s[3 * R_ + j]);
    float c = fg * prev_c[idx] + ig * gt;
    out_c[idx] = c;
    g_nexth[idx] = og * tanhf(c);
}

// ---------------- top_h = attres + next_h ----------------
__global__ void add_toph(float* __restrict__ out_h)
{
    int idx = blockIdx.x * 256 + threadIdx.x;
    if (idx >= B_ * R_) return;
    out_h[idx] = g_attres[idx] + g_nexth[idx];
}

// ---------------- log_softmax in-place over V ----------------
__global__ void log_softmax_kernel(float* __restrict__ logits)
{
    const int b = blockIdx.x, tid = threadIdx.x;  // 512 threads
    float* row = logits + (size_t)b * V_;
    __shared__ float rbuf[512];

    float mx = -1e30f;
    for (int i = tid; i < V_; i += 512) mx = fmaxf(mx, row[i]);
    rbuf[tid] = mx;
    __syncthreads();
    for (int off = 256; off > 0; off >>= 1) {
        if (tid < off) rbuf[tid] = fmaxf(rbuf[tid], rbuf[tid + off]);
        __syncthreads();
    }
    mx = rbuf[0];
    __syncthreads();
    float sum = 0.f;
    for (int i = tid; i < V_; i += 512) sum += __expf(row[i] - mx);
    rbuf[tid] = sum;
    __syncthreads();
    for (int off = 256; off > 0; off >>= 1) {
        if (tid < off) rbuf[tid] += rbuf[tid + off];
        __syncthreads();
    }
    float lse = mx + logf(rbuf[0]);
    for (int i = tid; i < V_; i += 512) row[i] -= lse;
}

// ---------------- host launch ----------------
extern "C" void kernel_launch(void* const* d_in, const int* in_sizes, int n_in,
                              void* d_out, int out_size)
{
    const float* x      = (const float*)d_in[0];
    const float* att    = (const float*)d_in[1];
    const float* prev_c = (const float*)d_in[2];
    const float* prev_h = (const float*)d_in[3];
    const float* W_a2a  = (const float*)d_in[4];  const float* b_a2a  = (const float*)d_in[5];
    const float* W_h2a  = (const float*)d_in[6];  const float* b_h2a  = (const float*)d_in[7];
    const float* W_d2d  = (const float*)d_in[8];  const float* b_d2d  = (const float*)d_in[9];
    const float* W_i2h  = (const float*)d_in[10]; const float* b_i2h  = (const float*)d_in[11];
    const float* W_a2h  = (const float*)d_in[12]; const float* b_a2h  = (const float*)d_in[13];
    const float* W_h2h  = (const float*)d_in[14]; const float* b_h2h  = (const float*)d_in[15];
    const float* W_a2a1 = (const float*)d_in[16]; const float* b_a2a1 = (const float*)d_in[17];
    const float* W_h2a1 = (const float*)d_in[18]; const float* b_h2a1 = (const float*)d_in[19];
    const float* W_d2d1 = (const float*)d_in[20]; const float* b_d2d1 = (const float*)d_in[21];
    const float* W_proj = (const float*)d_in[22]; const float* b_proj = (const float*)d_in[23];

    float* out   = (float*)d_out;
    float* out_c = out;                  // next_c  [B,R]
    float* out_h = out + B_ * R_;        // top_h   [B,R]
    float* out_l = out + 2 * B_ * R_;    // logsoft [B,V]

    float *ah_p, *attres_p, *nexth_p;
    cudaGetSymbolAddress((void**)&ah_p,     g_ah);
    cudaGetSymbolAddress((void**)&attres_p, g_attres);
    cudaGetSymbolAddress((void**)&nexth_p,  g_nexth);

    const dim3 blk(256);

    // ---- attend #0 (uses prev_h) ----
    sgemm_bias<<<dim3((A_ + 63) / 64, (B_ + 63) / 64), blk>>>(prev_h, W_h2a, b_h2a, nullptr, ah_p, B_, A_, R_);
    attend_scores<<<(B_ * A_) / 64, blk>>>(att, W_a2a, b_a2a, W_d2d, b_d2d);
    attend_apply<<<B_, blk>>>(att, attres_p);

    // ---- LSTM gates ----
    gates_gemm<<<dim3((4 * R_) / 64, B_ / 64), blk>>>(x, W_i2h, prev_h, W_h2h, attres_p, W_a2h,
                                                      b_i2h, b_h2h, b_a2h);
    lstm_cell<<<(B_ * R_ + 255) / 256, blk>>>(prev_c, out_c);

    // ---- attend #1 (uses next_h) ----
    sgemm_bias<<<dim3((A_ + 63) / 64, (B_ + 63) / 64), blk>>>(nexth_p, W_h2a1, b_h2a1, nullptr, ah_p, B_, A_, R_);
    attend_scores<<<(B_ * A_) / 64, blk>>>(att, W_a2a1, b_a2a1, W_d2d1, b_d2d1);
    attend_apply<<<B_, blk>>>(att, attres_p);

    // ---- top_h, projection, log_softmax ----
    add_toph<<<(B_ * R_ + 255) / 256, blk>>>(out_h);
    sgemm_bias<<<dim3((V_ + 63) / 64, (B_ + 63) / 64), blk>>>(out_h, W_proj, b_proj, nullptr, out_l, B_, V_, R_);
    log_softmax_kernel<<<B_, 512>>>(out_l);
}